// round 1
// baseline (speedup 1.0000x reference)
#include <cuda_runtime.h>

// Problem constants (from reference):
//   B=32, N=128, FI=768, FO=128
// Output y[b,c] = b_fc[c] + sum_o W_fc[c,o] * dot(h[b,0,:], W_emb[o,:])
// The TreeLSTM scan in the reference is dead code (its result is deleted);
// adjacency and all recurrent weights do not affect the output.

#define B_  32
#define N_  128
#define FI_ 768
#define FO_ 128

__global__ __launch_bounds__(FO_, 1)
void rvnn_head_kernel(const float* __restrict__ h,      // [B,N,FI]
                      const float* __restrict__ W_emb,  // [FO,FI]
                      const float* __restrict__ W_fc,   // [2,FO]
                      const float* __restrict__ b_fc,   // [2]
                      float* __restrict__ y)            // [B,2]
{
    const int b = blockIdx.x;      // batch
    const int o = threadIdx.x;     // output feature (0..127)

    __shared__ float4 sh_h[FI_ / 4];      // h[b,0,:] staged, 768 floats
    __shared__ float  s0[FO_], s1[FO_];   // reduction buffers

    // Coalesced stage of h[b,0,:] (row 0 of this batch): 192 float4.
    const float4* hrow = reinterpret_cast<const float4*>(h + (size_t)b * N_ * FI_);
    #pragma unroll
    for (int i = o; i < FI_ / 4; i += FO_)
        sh_h[i] = hrow[i];
    __syncthreads();

    // Each thread: dot(h[b,0,:], W_emb[o,:]) over 768 elements via float4.
    const float4* wrow = reinterpret_cast<const float4*>(W_emb + (size_t)o * FI_);
    float acc = 0.0f;
    #pragma unroll 8
    for (int i = 0; i < FI_ / 4; ++i) {
        float4 hv = sh_h[i];
        float4 wv = wrow[i];
        acc = fmaf(hv.x, wv.x, acc);
        acc = fmaf(hv.y, wv.y, acc);
        acc = fmaf(hv.z, wv.z, acc);
        acc = fmaf(hv.w, wv.w, acc);
    }

    // Contract with W_fc rows: y[b,c] = b_fc[c] + sum_o W_fc[c,o]*acc_o
    s0[o] = acc * W_fc[0 * FO_ + o];
    s1[o] = acc * W_fc[1 * FO_ + o];
    __syncthreads();

    // Tree reduction over 128 entries.
    #pragma unroll
    for (int stride = FO_ / 2; stride >= 1; stride >>= 1) {
        if (o < stride) {
            s0[o] += s0[o + stride];
            s1[o] += s1[o + stride];
        }
        __syncthreads();
    }

    if (o == 0) {
        y[b * 2 + 0] = s0[0] + b_fc[0];
        y[b * 2 + 1] = s1[0] + b_fc[1];
    }
}

extern "C" void kernel_launch(void* const* d_in, const int* in_sizes, int n_in,
                              void* d_out, int out_size)
{
    // metadata order: h, adj, W_emb, W_ioux, b_ioux, W_iouh, b_iouh,
    //                 W_coux, b_coux, W_couh, b_couh, W_fc, b_fc
    const float* h     = (const float*)d_in[0];
    const float* W_emb = (const float*)d_in[2];
    const float* W_fc  = (const float*)d_in[11];
    const float* b_fc  = (const float*)d_in[12];
    float* y = (float*)d_out;

    rvnn_head_kernel<<<B_, FO_>>>(h, W_emb, W_fc, b_fc, y);
}

// round 2
// speedup vs baseline: 2.1505x; 2.1505x over previous
#include <cuda_runtime.h>

// Reference reduces to: y[b,c] = b_fc[c] + sum_o W_fc[c,o] * dot(h[b,0,:], W_emb[o,:])
// (the TreeLSTM scan result is deleted; adj and recurrent weights are dead).
// B=32, N=128, FI=768, FO=128.

#define B_  32
#define N_  128
#define FI_ 768
#define FO_ 128
#define NT_ 1024   // 32 warps per block

__global__ __launch_bounds__(NT_, 1)
void rvnn_head_kernel(const float* __restrict__ h,      // [B,N,FI]
                      const float* __restrict__ W_emb,  // [FO,FI]
                      const float* __restrict__ W_fc,   // [2,FO]
                      const float* __restrict__ b_fc,   // [2]
                      float* __restrict__ y)            // [B,2]
{
    const int b    = blockIdx.x;
    const int tid  = threadIdx.x;
    const int warp = tid >> 5;
    const int lane = tid & 31;

    __shared__ float4 sh_h[FI_ / 4];     // 192 float4 = h[b,0,:]
    __shared__ float  s0[FO_], s1[FO_];

    // Stage h[b,0,:] — one coalesced pass (threads 0..191 active).
    const float4* hrow = reinterpret_cast<const float4*>(h + (size_t)b * N_ * FI_);
    if (tid < FI_ / 4)
        sh_h[tid] = hrow[tid];
    __syncthreads();

    // Hoist this lane's h chunks into registers (reused across 4 passes).
    float4 hv[6];
    #pragma unroll
    for (int i = 0; i < 6; ++i)
        hv[i] = sh_h[i * 32 + lane];

    // 4 passes: one warp per W_emb row, 32 rows per pass.
    #pragma unroll
    for (int pass = 0; pass < 4; ++pass) {
        const int o = pass * 32 + warp;
        const float4* wrow = reinterpret_cast<const float4*>(W_emb + (size_t)o * FI_);

        float acc = 0.0f;
        #pragma unroll
        for (int i = 0; i < 6; ++i) {
            // 32 lanes * 16B = 512B contiguous per warp-load: fully coalesced.
            float4 wv = wrow[i * 32 + lane];
            acc = fmaf(hv[i].x, wv.x, acc);
            acc = fmaf(hv[i].y, wv.y, acc);
            acc = fmaf(hv[i].z, wv.z, acc);
            acc = fmaf(hv[i].w, wv.w, acc);
        }

        // Warp-level sum.
        #pragma unroll
        for (int off = 16; off > 0; off >>= 1)
            acc += __shfl_down_sync(0xffffffffu, acc, off);

        if (lane == 0) {
            s0[o] = acc * W_fc[o];          // W_fc row 0
            s1[o] = acc * W_fc[FO_ + o];    // W_fc row 1
        }
    }
    __syncthreads();

    // Final 128-element reduction by warp 0.
    if (warp == 0) {
        float a0 = s0[lane] + s0[lane + 32] + s0[lane + 64] + s0[lane + 96];
        float a1 = s1[lane] + s1[lane + 32] + s1[lane + 64] + s1[lane + 96];
        #pragma unroll
        for (int off = 16; off > 0; off >>= 1) {
            a0 += __shfl_down_sync(0xffffffffu, a0, off);
            a1 += __shfl_down_sync(0xffffffffu, a1, off);
        }
        if (lane == 0) {
            y[b * 2 + 0] = a0 + b_fc[0];
            y[b * 2 + 1] = a1 + b_fc[1];
        }
    }
}

extern "C" void kernel_launch(void* const* d_in, const int* in_sizes, int n_in,
                              void* d_out, int out_size)
{
    // metadata order: h, adj, W_emb, W_ioux, b_ioux, W_iouh, b_iouh,
    //                 W_coux, b_coux, W_couh, b_couh, W_fc, b_fc
    const float* h     = (const float*)d_in[0];
    const float* W_emb = (const float*)d_in[2];
    const float* W_fc  = (const float*)d_in[11];
    const float* b_fc  = (const float*)d_in[12];
    float* y = (float*)d_out;

    rvnn_head_kernel<<<B_, NT_>>>(h, W_emb, W_fc, b_fc, y);
}